// round 9
// baseline (speedup 1.0000x reference)
#include <cuda_runtime.h>
#include <cuda_bf16.h>
#include <limits.h>

// Problem constants (from reference setup_inputs):
//   B=64 batches, K=16 candidates, L_cand=32, L_src=64, pad_id=0
//   vocab V=50257 < 2^16 -> tokens fit in 16 bits (packed compares safe)
#define B_SZ   64
#define K_SZ   16
#define LC_SZ  32
#define LS_SZ  64

#define FULL_MASK 0xFFFFFFFFu
#define HALF_MASK 0x0000FFFFu

// One CTA per batch, one warp per candidate k (16 warps = 512 threads).
// Lane l holds src pair (src[2l], src[2l+1]) packed into one reg (16b halves).
// Pre-barrier (all warps):
//   dot[k]: broadcast duplicated candidate halfwords; per iter one __vcmpeq2
//           (0xFFFF == -1 per matching half) folded with __vsub2 into 4
//           independent accumulators (breaks the 32-deep add chain).
//           cand pad -> 0xFFFF sentinel (> max token, != src pad 0).
//   c2[k] : __match_any + popc -> cn = sqrt(c2) hoisted off the tail.
//   r2    : distributed — warp w broadcasts pairs of lanes w and w+16
//           (positions {2w,2w+1,32+2w,32+2w+1}; 16 warps cover all 64).
//   REDUX; lane0 -> smem ((dotf,cn) packed as float2); ONE barrier.
// Post-barrier (warp 0 only): r2 reduce, score, stable rank sort,
//   scores_sorted, winner token reload (L1-hot) + tokens/length writes.
__global__ void __launch_bounds__(512, 2)
ngram_rerank_kernel(const int* __restrict__ cand,   // [B, K, LC]
                    const int* __restrict__ src,    // [B, LS]
                    float* __restrict__ out_f,      // full fp32 layout, or null
                    int*   __restrict__ out_i)      // tokens-only int32, or null
{
    const int b    = blockIdx.x;
    const int tid  = threadIdx.x;
    const int warp = tid >> 5;     // candidate index k
    const int lane = tid & 31;

    __shared__ float2 sm_dc[K_SZ];    // ((float)dot[k], sqrt(c2[k]))
    __shared__ int    sm_r2p[K_SZ];   // r2 partial per warp

    // ---- coalesced loads: src as int2 (one LDG.64), cand one LDG.32 ----
    const int2 sp = reinterpret_cast<const int2*>(src + b * LS_SZ)[lane];
    const int sA = sp.x;   // src[2*lane]
    const int sB = sp.y;   // src[2*lane+1]
    const int t  = cand[b * (K_SZ * LC_SZ) + warp * LC_SZ + lane];

    // ---- dot[k]: packed 16-bit compares, 4 independent accumulators ----
    // sPK: (sB<<16)|sA ; src pads stay 0 (valid cand tokens are >=1).
    // cand pad -> 0xFFFF sentinel (max valid token 50256 < 0xFFFF).
    const unsigned sPK  = ((unsigned)sB << 16) | ((unsigned)sA & 0xFFFFu);
    const unsigned t16  = (t != 0) ? (unsigned)t : 0xFFFFu;
    const unsigned tdup = t16 * 0x00010001u;   // duplicate into both halves
    unsigned a0 = 0, a1 = 0, a2 = 0, a3 = 0;   // per-half counts (<=32 each)
    #pragma unroll
    for (int i = 0; i < 32; i += 4) {
        // vcmpeq2 -> 0xFFFF (== -1) per matching half; vsub2 increments halves
        a0 = __vsub2(a0, __vcmpeq2(__shfl_sync(FULL_MASK, tdup, i + 0), sPK));
        a1 = __vsub2(a1, __vcmpeq2(__shfl_sync(FULL_MASK, tdup, i + 1), sPK));
        a2 = __vsub2(a2, __vcmpeq2(__shfl_sync(FULL_MASK, tdup, i + 2), sPK));
        a3 = __vsub2(a3, __vcmpeq2(__shfl_sync(FULL_MASK, tdup, i + 3), sPK));
    }
    const unsigned dacc = __vadd2(__vadd2(a0, a1), __vadd2(a2, a3));
    const int d = (int)((dacc & 0xFFFFu) + (dacc >> 16));

    // ---- ||c_k||^2 via match groups ----
    const unsigned mm = __match_any_sync(FULL_MASK, t);
    const int c2_val  = (t != 0) ? __popc(mm) : 0;

    // ---- r2 partial: warp w broadcasts pairs of lanes w and w+16 ----
    // covers src positions {2w, 2w+1, 32+2w, 32+2w+1}; 16 warps -> all 64.
    // lane-side sentinels: unique negatives per position (pads match nothing)
    const int sAm = (sA != 0) ? sA : ~(2 * lane);       // unique in [-64, -1]
    const int sBm = (sB != 0) ? sB : ~(2 * lane + 1);
    int cv0 = __shfl_sync(FULL_MASK, sAm, warp);        // src[2w]
    int cv1 = __shfl_sync(FULL_MASK, sBm, warp);        // src[2w+1]
    int cv2 = __shfl_sync(FULL_MASK, sAm, warp + 16);   // src[32+2w]
    int cv3 = __shfl_sync(FULL_MASK, sBm, warp + 16);   // src[32+2w+1]
    cv0 = (cv0 < 0) ? INT_MIN : cv0;    // broadcast-side pads match nothing
    cv1 = (cv1 < 0) ? INT_MIN : cv1;
    cv2 = (cv2 < 0) ? INT_MIN : cv2;
    cv3 = (cv3 < 0) ? INT_MIN : cv3;
    const int a = (cv0 == sAm) + (cv0 == sBm)
                + (cv1 == sAm) + (cv1 == sBm)
                + (cv2 == sAm) + (cv2 == sBm)
                + (cv3 == sAm) + (cv3 == sBm);

    const int dot = __reduce_add_sync(FULL_MASK, d);
    const int c2  = __reduce_add_sync(FULL_MASK, c2_val);
    const int r2p = __reduce_add_sync(FULL_MASK, a);

    if (lane == 0) {
        sm_dc[warp]  = make_float2((float)dot, __fsqrt_rn((float)c2));
        sm_r2p[warp] = r2p;
    }
    __syncthreads();

    if (warp != 0) return;   // warps 1..15 done

    // ---- warp 0 finishes alone ----
    int kwin_l = 0;
    if (lane < K_SZ) {
        const int r2 = __reduce_add_sync(HALF_MASK, sm_r2p[lane]);
        const float2 dc = sm_dc[lane];          // one LDS.64
        const float rn = __fsqrt_rn((float)r2);
        const float si = __fsub_rn(1.0f,
            __fdiv_rn(dc.x, __fmul_rn(rn, dc.y)));

        // stable descending rank (matches jnp.argsort(-scores), stable)
        int rank = 0;
        #pragma unroll
        for (int j = 0; j < K_SZ; j++) {
            const float sj = __shfl_sync(HALF_MASK, si, j);
            rank += (sj > si) || (sj == si && j < lane);
        }
        if (out_f != nullptr)
            out_f[B_SZ * LC_SZ + B_SZ + b * K_SZ + rank] = si;  // scores_sorted

        const unsigned winb = __ballot_sync(HALF_MASK, rank == 0);
        kwin_l = __ffs(winb) - 1;
    }
    const int kwin = __shfl_sync(FULL_MASK, kwin_l, 0);

    // Winning candidate's tokens: line was just read by warp kwin -> L1 hit.
    const int tw = cand[b * (K_SZ * LC_SZ) + kwin * LC_SZ + lane];
    const unsigned nb = __ballot_sync(FULL_MASK, tw != 0);

    if (out_f != nullptr) {
        out_f[b * LC_SZ + lane] = (float)tw;                    // tokens
        if (lane == 0)
            out_f[B_SZ * LC_SZ + b] = (float)__popc(nb);        // length
    } else {
        out_i[b * LC_SZ + lane] = tw;
    }
}

extern "C" void kernel_launch(void* const* d_in, const int* in_sizes, int n_in,
                              void* d_out, int out_size)
{
    // Identify tensors by element count (robust to scalar inputs in the list):
    //   candidates: 64*16*32 = 32768,  src_ids: 64*64 = 4096
    const int* cand = nullptr;
    const int* src  = nullptr;
    for (int i = 0; i < n_in; i++) {
        if (in_sizes[i] == B_SZ * K_SZ * LC_SZ) cand = (const int*)d_in[i];
        else if (in_sizes[i] == B_SZ * LS_SZ)   src  = (const int*)d_in[i];
    }

    if (out_size == B_SZ * LC_SZ) {
        ngram_rerank_kernel<<<B_SZ, 512>>>(cand, src, nullptr, (int*)d_out);
    } else {
        ngram_rerank_kernel<<<B_SZ, 512>>>(cand, src, (float*)d_out, nullptr);
    }
}

// round 10
// speedup vs baseline: 1.0337x; 1.0337x over previous
#include <cuda_runtime.h>
#include <cuda_bf16.h>
#include <limits.h>

// Problem constants (from reference setup_inputs):
//   B=64 batches, K=16 candidates, L_cand=32, L_src=64, pad_id=0
//   vocab V=50257 < 2^16 -> tokens fit in 16 bits (packed compares safe)
#define B_SZ   64
#define K_SZ   16
#define LC_SZ  32
#define LS_SZ  64

#define FULL_MASK 0xFFFFFFFFu
#define HALF_MASK 0x0000FFFFu

// One CTA per batch, one warp per candidate k (16 warps = 512 threads).
// Lane l holds src pair (src[2l], src[2l+1]) packed into one reg (16b halves).
// Pre-barrier (all warps):
//   dot[k]: broadcast duplicated candidate halfwords; one __vcmpeq2 + __vsub2
//           per src pair (0xFFFF == -1 per matching half), 2 independent accs.
//           cand pad -> 0xFFFF sentinel (> max token 50256, != src pad 0).
//   c2[k] : __match_any + popc.
//   r2    : distributed — warp w broadcasts pairs of lanes w and w+16
//           (positions {2w,2w+1,32+2w,32+2w+1}; 16 warps cover all 64).
//   ONE fused REDUX: d (<=64 -> sum<=2048, bits[0:12)) | c2 (<=32 -> sum<=1024,
//   bits[12:23)) | a (<=8 -> sum<=256, bits[23:32)). lane0 unpacks -> smem
//   ((float)dot, sqrt(c2)) as float2 + r2 partial; ONE barrier.
// Post-barrier (warp 0 only): r2 reduce, score, stable rank sort,
//   scores_sorted, winner token reload (L1-hot) + tokens/length writes.
__global__ void __launch_bounds__(512, 2)
ngram_rerank_kernel(const int* __restrict__ cand,   // [B, K, LC]
                    const int* __restrict__ src,    // [B, LS]
                    float* __restrict__ out_f,      // full fp32 layout, or null
                    int*   __restrict__ out_i)      // tokens-only int32, or null
{
    const int b    = blockIdx.x;
    const int tid  = threadIdx.x;
    const int warp = tid >> 5;     // candidate index k
    const int lane = tid & 31;

    __shared__ float2 sm_dc[K_SZ];    // ((float)dot[k], sqrt(c2[k]))
    __shared__ int    sm_r2p[K_SZ];   // r2 partial per warp

    // ---- coalesced loads: src as int2 (one LDG.64), cand one LDG.32 ----
    const int2 sp = reinterpret_cast<const int2*>(src + b * LS_SZ)[lane];
    const int sA = sp.x;   // src[2*lane]
    const int sB = sp.y;   // src[2*lane+1]
    const int t  = cand[b * (K_SZ * LC_SZ) + warp * LC_SZ + lane];

    // ---- dot[k]: packed 16-bit compares, 2 independent accumulators ----
    const unsigned sPK  = ((unsigned)sB << 16) | ((unsigned)sA & 0xFFFFu);
    const unsigned t16  = (t != 0) ? (unsigned)t : 0xFFFFu;
    const unsigned tdup = t16 * 0x00010001u;   // duplicate into both halves
    unsigned a0 = 0, a1 = 0;                   // per-half counts (<=32 each)
    #pragma unroll
    for (int i = 0; i < 32; i += 2) {
        // vcmpeq2 -> 0xFFFF (== -1) per matching half; vsub2 increments halves
        a0 = __vsub2(a0, __vcmpeq2(__shfl_sync(FULL_MASK, tdup, i + 0), sPK));
        a1 = __vsub2(a1, __vcmpeq2(__shfl_sync(FULL_MASK, tdup, i + 1), sPK));
    }
    const unsigned dacc = __vadd2(a0, a1);
    const int d = (int)((dacc & 0xFFFFu) + (dacc >> 16));   // <= 64

    // ---- ||c_k||^2 via match groups ----
    const unsigned mm = __match_any_sync(FULL_MASK, t);
    const int c2_val  = (t != 0) ? __popc(mm) : 0;          // <= 32

    // ---- r2 partial: warp w broadcasts pairs of lanes w and w+16 ----
    // covers src positions {2w, 2w+1, 32+2w, 32+2w+1}; 16 warps -> all 64.
    // lane-side sentinels: unique negatives per position (pads match nothing)
    const int sAm = (sA != 0) ? sA : ~(2 * lane);       // unique in [-64, -1]
    const int sBm = (sB != 0) ? sB : ~(2 * lane + 1);
    int cv0 = __shfl_sync(FULL_MASK, sAm, warp);        // src[2w]
    int cv1 = __shfl_sync(FULL_MASK, sBm, warp);        // src[2w+1]
    int cv2 = __shfl_sync(FULL_MASK, sAm, warp + 16);   // src[32+2w]
    int cv3 = __shfl_sync(FULL_MASK, sBm, warp + 16);   // src[32+2w+1]
    cv0 = (cv0 < 0) ? INT_MIN : cv0;    // broadcast-side pads match nothing
    cv1 = (cv1 < 0) ? INT_MIN : cv1;
    cv2 = (cv2 < 0) ? INT_MIN : cv2;
    cv3 = (cv3 < 0) ? INT_MIN : cv3;
    const int a = (cv0 == sAm) + (cv0 == sBm)
                + (cv1 == sAm) + (cv1 == sBm)
                + (cv2 == sAm) + (cv2 == sBm)
                + (cv3 == sAm) + (cv3 == sBm);              // <= 8

    // ---- ONE fused REDUX: [0:12) dot, [12:23) c2, [23:32) r2p ----
    const unsigned packed = (unsigned)d
                          | ((unsigned)c2_val << 12)
                          | ((unsigned)a      << 23);
    const unsigned red = __reduce_add_sync(FULL_MASK, packed);

    if (lane == 0) {
        const int dot = (int)(red & 0xFFFu);           // sum <= 2048
        const int c2  = (int)((red >> 12) & 0x7FFu);   // sum <= 1024
        const int r2p = (int)(red >> 23);              // sum <= 256
        sm_dc[warp]  = make_float2((float)dot, __fsqrt_rn((float)c2));
        sm_r2p[warp] = r2p;
    }
    __syncthreads();

    if (warp != 0) return;   // warps 1..15 done

    // ---- warp 0 finishes alone ----
    int kwin_l = 0;
    if (lane < K_SZ) {
        const int r2 = __reduce_add_sync(HALF_MASK, sm_r2p[lane]);
        const float2 dc = sm_dc[lane];          // one LDS.64
        const float rn = __fsqrt_rn((float)r2);
        const float si = __fsub_rn(1.0f,
            __fdiv_rn(dc.x, __fmul_rn(rn, dc.y)));

        // stable descending rank (matches jnp.argsort(-scores), stable)
        int rank = 0;
        #pragma unroll
        for (int j = 0; j < K_SZ; j++) {
            const float sj = __shfl_sync(HALF_MASK, si, j);
            rank += (sj > si) || (sj == si && j < lane);
        }
        if (out_f != nullptr)
            out_f[B_SZ * LC_SZ + B_SZ + b * K_SZ + rank] = si;  // scores_sorted

        const unsigned winb = __ballot_sync(HALF_MASK, rank == 0);
        kwin_l = __ffs(winb) - 1;
    }
    const int kwin = __shfl_sync(FULL_MASK, kwin_l, 0);

    // Winning candidate's tokens: line was just read by warp kwin -> L1 hit.
    const int tw = cand[b * (K_SZ * LC_SZ) + kwin * LC_SZ + lane];
    const unsigned nb = __ballot_sync(FULL_MASK, tw != 0);

    if (out_f != nullptr) {
        out_f[b * LC_SZ + lane] = (float)tw;                    // tokens
        if (lane == 0)
            out_f[B_SZ * LC_SZ + b] = (float)__popc(nb);        // length
    } else {
        out_i[b * LC_SZ + lane] = tw;
    }
}

extern "C" void kernel_launch(void* const* d_in, const int* in_sizes, int n_in,
                              void* d_out, int out_size)
{
    // Identify tensors by element count (robust to scalar inputs in the list):
    //   candidates: 64*16*32 = 32768,  src_ids: 64*64 = 4096
    const int* cand = nullptr;
    const int* src  = nullptr;
    for (int i = 0; i < n_in; i++) {
        if (in_sizes[i] == B_SZ * K_SZ * LC_SZ) cand = (const int*)d_in[i];
        else if (in_sizes[i] == B_SZ * LS_SZ)   src  = (const int*)d_in[i];
    }

    if (out_size == B_SZ * LC_SZ) {
        ngram_rerank_kernel<<<B_SZ, 512>>>(cand, src, nullptr, (int*)d_out);
    } else {
        ngram_rerank_kernel<<<B_SZ, 512>>>(cand, src, (float*)d_out, nullptr);
    }
}

// round 11
// speedup vs baseline: 1.0386x; 1.0048x over previous
#include <cuda_runtime.h>
#include <cuda_bf16.h>
#include <limits.h>

// Problem constants (from reference setup_inputs):
//   B=64 batches, K=16 candidates, L_cand=32, L_src=64, pad_id=0
//   vocab V=50257 < 2^16 -> tokens fit in 16 bits (packed compares safe)
#define B_SZ   64
#define K_SZ   16
#define LC_SZ  32
#define LS_SZ  64

#define FULL_MASK 0xFFFFFFFFu
#define HALF_MASK 0x0000FFFFu

// One CTA per batch, one warp per candidate k (16 warps = 512 threads).
// Lane l holds src pair (src[2l], src[2l+1]) packed into one reg (16b halves).
// Pre-barrier (all warps):
//   - stash this warp's candidate tokens to smem (tail reads LDS, not LDG)
//   - dot[k]: broadcast duplicated candidate halfwords; one __vcmpeq2 + __vsub2
//     per src pair (0xFFFF == -1 per matching half), 2 independent accums.
//     cand pad -> 0xFFFF sentinel (> max token 50256, != src pad 0).
//   - c2[k]: __match_any + popc.
//   - r2: distributed — warp w broadcasts pairs of lanes w and w+16
//     (positions {2w,2w+1,32+2w,32+2w+1}; 16 warps cover all 64).
//   - ONE fused REDUX: d in bits[0:12) (sum<=2048), c2 in [12:23) (sum<=1024),
//     r2p in [23:32) (sum<=256). lane0 unpacks -> smem; ONE barrier.
// Post-barrier (warp 0 only): r2 reduce, score, stable rank sort,
//   scores_sorted, winner tokens from smem (LDS) + tokens/length writes.
__global__ void __launch_bounds__(512, 2)
ngram_rerank_kernel(const int* __restrict__ cand,   // [B, K, LC]
                    const int* __restrict__ src,    // [B, LS]
                    float* __restrict__ out_f,      // full fp32 layout, or null
                    int*   __restrict__ out_i)      // tokens-only int32, or null
{
    const int b    = blockIdx.x;
    const int tid  = threadIdx.x;
    const int warp = tid >> 5;     // candidate index k
    const int lane = tid & 31;

    __shared__ float2 sm_dc[K_SZ];          // ((float)dot[k], sqrt(c2[k]))
    __shared__ int    sm_r2p[K_SZ];         // r2 partial per warp
    __shared__ int    sm_tok[K_SZ * LC_SZ]; // candidate token stash

    // ---- coalesced loads: src as int2 (one LDG.64), cand one LDG.32 ----
    const int2 sp = reinterpret_cast<const int2*>(src + b * LS_SZ)[lane];
    const int sA = sp.x;   // src[2*lane]
    const int sB = sp.y;   // src[2*lane+1]
    const int t  = cand[b * (K_SZ * LC_SZ) + warp * LC_SZ + lane];
    sm_tok[warp * LC_SZ + lane] = t;        // stash for the tail (off crit path)

    // ---- dot[k]: packed 16-bit compares, 2 independent accumulators ----
    const unsigned sPK  = ((unsigned)sB << 16) | ((unsigned)sA & 0xFFFFu);
    const unsigned t16  = (t != 0) ? (unsigned)t : 0xFFFFu;
    const unsigned tdup = t16 * 0x00010001u;   // duplicate into both halves
    unsigned a0 = 0, a1 = 0;                   // per-half counts (<=32 each)
    #pragma unroll
    for (int i = 0; i < 32; i += 2) {
        // vcmpeq2 -> 0xFFFF (== -1) per matching half; vsub2 increments halves
        a0 = __vsub2(a0, __vcmpeq2(__shfl_sync(FULL_MASK, tdup, i + 0), sPK));
        a1 = __vsub2(a1, __vcmpeq2(__shfl_sync(FULL_MASK, tdup, i + 1), sPK));
    }
    const unsigned dacc = __vadd2(a0, a1);
    const int d = (int)((dacc & 0xFFFFu) + (dacc >> 16));   // <= 64

    // ---- ||c_k||^2 via match groups ----
    const unsigned mm = __match_any_sync(FULL_MASK, t);
    const int c2_val  = (t != 0) ? __popc(mm) : 0;          // <= 32

    // ---- r2 partial: warp w broadcasts pairs of lanes w and w+16 ----
    // covers src positions {2w, 2w+1, 32+2w, 32+2w+1}; 16 warps -> all 64.
    // lane-side sentinels: unique negatives per position (pads match nothing)
    const int sAm = (sA != 0) ? sA : ~(2 * lane);       // unique in [-64, -1]
    const int sBm = (sB != 0) ? sB : ~(2 * lane + 1);
    int cv0 = __shfl_sync(FULL_MASK, sAm, warp);        // src[2w]
    int cv1 = __shfl_sync(FULL_MASK, sBm, warp);        // src[2w+1]
    int cv2 = __shfl_sync(FULL_MASK, sAm, warp + 16);   // src[32+2w]
    int cv3 = __shfl_sync(FULL_MASK, sBm, warp + 16);   // src[32+2w+1]
    cv0 = (cv0 < 0) ? INT_MIN : cv0;    // broadcast-side pads match nothing
    cv1 = (cv1 < 0) ? INT_MIN : cv1;
    cv2 = (cv2 < 0) ? INT_MIN : cv2;
    cv3 = (cv3 < 0) ? INT_MIN : cv3;
    const int a = (cv0 == sAm) + (cv0 == sBm)
                + (cv1 == sAm) + (cv1 == sBm)
                + (cv2 == sAm) + (cv2 == sBm)
                + (cv3 == sAm) + (cv3 == sBm);              // <= 8

    // ---- ONE fused REDUX: [0:12) dot, [12:23) c2, [23:32) r2p ----
    const unsigned packed = (unsigned)d
                          | ((unsigned)c2_val << 12)
                          | ((unsigned)a      << 23);
    const unsigned red = __reduce_add_sync(FULL_MASK, packed);

    if (lane == 0) {
        const int dot = (int)(red & 0xFFFu);           // sum <= 2048
        const int c2  = (int)((red >> 12) & 0x7FFu);   // sum <= 1024
        const int r2p = (int)(red >> 23);              // sum <= 256
        sm_dc[warp]  = make_float2((float)dot, __fsqrt_rn((float)c2));
        sm_r2p[warp] = r2p;
    }
    __syncthreads();

    if (warp != 0) return;   // warps 1..15 done

    // ---- warp 0 finishes alone ----
    int kwin_l = 0;
    if (lane < K_SZ) {
        const int r2 = __reduce_add_sync(HALF_MASK, sm_r2p[lane]);
        const float2 dc = sm_dc[lane];          // one LDS.64
        const float rn = __fsqrt_rn((float)r2);
        const float si = __fsub_rn(1.0f,
            __fdiv_rn(dc.x, __fmul_rn(rn, dc.y)));

        // stable descending rank (matches jnp.argsort(-scores), stable)
        int rank = 0;
        #pragma unroll
        for (int j = 0; j < K_SZ; j++) {
            const float sj = __shfl_sync(HALF_MASK, si, j);
            rank += (sj > si) || (sj == si && j < lane);
        }
        if (out_f != nullptr)
            out_f[B_SZ * LC_SZ + B_SZ + b * K_SZ + rank] = si;  // scores_sorted

        const unsigned winb = __ballot_sync(HALF_MASK, rank == 0);
        kwin_l = __ffs(winb) - 1;
    }
    const int kwin = __shfl_sync(FULL_MASK, kwin_l, 0);

    // Winning candidate's tokens from the smem stash (LDS, not LDG).
    const int tw = sm_tok[kwin * LC_SZ + lane];
    const unsigned nb = __ballot_sync(FULL_MASK, tw != 0);

    if (out_f != nullptr) {
        out_f[b * LC_SZ + lane] = (float)tw;                    // tokens
        if (lane == 0)
            out_f[B_SZ * LC_SZ + b] = (float)__popc(nb);        // length
    } else {
        out_i[b * LC_SZ + lane] = tw;
    }
}

extern "C" void kernel_launch(void* const* d_in, const int* in_sizes, int n_in,
                              void* d_out, int out_size)
{
    // Identify tensors by element count (robust to scalar inputs in the list):
    //   candidates: 64*16*32 = 32768,  src_ids: 64*64 = 4096
    const int* cand = nullptr;
    const int* src  = nullptr;
    for (int i = 0; i < n_in; i++) {
        if (in_sizes[i] == B_SZ * K_SZ * LC_SZ) cand = (const int*)d_in[i];
        else if (in_sizes[i] == B_SZ * LS_SZ)   src  = (const int*)d_in[i];
    }

    if (out_size == B_SZ * LC_SZ) {
        ngram_rerank_kernel<<<B_SZ, 512>>>(cand, src, nullptr, (int*)d_out);
    } else {
        ngram_rerank_kernel<<<B_SZ, 512>>>(cand, src, (float*)d_out, nullptr);
    }
}